// round 10
// baseline (speedup 1.0000x reference)
#include <cuda_runtime.h>
#include <cuda_bf16.h>
#include <math.h>
#include <stdint.h>

constexpr int kB   = 64;
constexpr int kIn  = 1024;
constexpr int kOut = 1024;
constexpr int kE   = 8;
constexpr int kH   = 8;

__device__ float g_part[kE * kB * kOut];   // per-expert scaled partials (e<7 only)
__device__ int   g_flag[16];               // per-o-tile arrival counters (self-resetting)

// ---------------------------------------------------------------------------
// helpers
// ---------------------------------------------------------------------------
__device__ __forceinline__ uint32_t smem_u32(const void* p) {
    uint32_t a;
    asm("{ .reg .u64 t; cvta.to.shared.u64 t, %1; cvt.u32.u64 %0, t; }"
        : "=r"(a) : "l"(p));
    return a;
}
__device__ __forceinline__ uint32_t swz(uint32_t off) {   // SW128 (Swizzle<3,4,3>)
    return off ^ ((off >> 3) & 0x70);
}
__device__ __forceinline__ void sts64(uint32_t addr, uint2 v) {
    asm volatile("st.shared.v2.u32 [%0], {%1,%2};" :: "r"(addr), "r"(v.x), "r"(v.y));
}
__device__ __forceinline__ void ldsm4(uint32_t* r, uint32_t addr) {
    asm volatile("ldmatrix.sync.aligned.m8n8.x4.shared.b16 {%0,%1,%2,%3}, [%4];"
                 : "=r"(r[0]), "=r"(r[1]), "=r"(r[2]), "=r"(r[3]) : "r"(addr));
}
__device__ __forceinline__ void mma16816(float* d, const uint32_t* a,
                                         uint32_t b0, uint32_t b1) {
    asm volatile(
        "mma.sync.aligned.m16n8k16.row.col.f32.bf16.bf16.f32 "
        "{%0,%1,%2,%3}, {%4,%5,%6,%7}, {%8,%9}, {%0,%1,%2,%3};"
        : "+f"(d[0]), "+f"(d[1]), "+f"(d[2]), "+f"(d[3])
        : "r"(a[0]), "r"(a[1]), "r"(a[2]), "r"(a[3]), "r"(b0), "r"(b1));
}
__device__ __forceinline__ void split4(float4 f, uint2& h, uint2& l) {
    __nv_bfloat162 h01 = __floats2bfloat162_rn(f.x, f.y);
    __nv_bfloat162 h23 = __floats2bfloat162_rn(f.z, f.w);
    float a0 = __bfloat162float(h01.x), a1 = __bfloat162float(h01.y);
    float a2 = __bfloat162float(h23.x), a3 = __bfloat162float(h23.y);
    __nv_bfloat162 l01 = __floats2bfloat162_rn(f.x - a0, f.y - a1);
    __nv_bfloat162 l23 = __floats2bfloat162_rn(f.z - a2, f.w - a3);
    h = make_uint2(*reinterpret_cast<uint32_t*>(&h01), *reinterpret_cast<uint32_t*>(&h23));
    l = make_uint2(*reinterpret_cast<uint32_t*>(&l01), *reinterpret_cast<uint32_t*>(&l23));
}

// ---------------------------------------------------------------------------
// R4 GEMM verbatim (+fused prep) with flag-based cross-CTA reduce epilogue.
// 128 CTAs x 256 thr. CTA tile m64(eo) x n64(b), KC=64, 2-stage smem,
// warp tile m32 x n16, single acc set, one sync per chunk.
// ---------------------------------------------------------------------------
constexpr int STAGE = 32768;
constexpr int AH = 0, AL = 8192, BH = 16384, BL = 24576;
constexpr int SMEM_TOTAL = 2 * STAGE;      // 65536
constexpr int CS_OFF = 17408;              // right after tr (64*68*4 bytes)

__global__ __launch_bounds__(256, 1)
void gemm_kernel(const float* __restrict__ x, const float* __restrict__ w,
                 const float* __restrict__ align_conv,
                 const float* __restrict__ W_ih, const float* __restrict__ b_ih,
                 const float* __restrict__ b_hh, const float* __restrict__ W_att,
                 const float* __restrict__ b_att, float* __restrict__ out) {
    extern __shared__ char smem[];
    const uint32_t sbase = smem_u32(smem);
    const int tid  = threadIdx.x;
    const int lane = tid & 31;
    const int wid  = tid >> 5;
    const int wm   = wid & 1;        // m half (32 rows)
    const int wn   = wid >> 1;       // n quarter (16 cols)
    const int m0   = blockIdx.x * 64;
    const int e    = blockIdx.x >> 4;
    const int t    = blockIdx.x & 15;
    const int ob   = t * 64;

    float acc[2][2][4];
    #pragma unroll
    for (int i = 0; i < 2; i++)
        #pragma unroll
        for (int j = 0; j < 2; j++)
            #pragma unroll
            for (int c = 0; c < 4; c++) acc[i][j][c] = 0.f;

    float sx[4] = {0.f, 0.f, 0.f, 0.f};

    const float4* wg = reinterpret_cast<const float4*>(w);
    const float4* xg = reinterpret_cast<const float4*>(x);
    int rw[4], cw[4];
    #pragma unroll
    for (int q = 0; q < 4; q++) { int j = tid + q * 256; rw[q] = j >> 4; cw[q] = j & 15; }
    uint32_t so[4];
    #pragma unroll
    for (int q = 0; q < 4; q++) so[q] = swz((uint32_t)(rw[q] * 128 + cw[q] * 8));

    float4 wr[4], xr[4];
    #pragma unroll
    for (int q = 0; q < 4; q++) {
        wr[q] = wg[(m0 + rw[q]) * 256 + cw[q]];
        xr[q] = xg[rw[q] * 256 + cw[q]];
    }

    for (int ch = 0; ch < 16; ch++) {
        const uint32_t sb = sbase + (uint32_t)((ch & 1) * STAGE);

        // convert + swizzled STS (also fold x row-sums for the fused prep)
        #pragma unroll
        for (int q = 0; q < 4; q++) {
            uint2 h, l;
            split4(wr[q], h, l);
            sts64(sb + AH + so[q], h);
            sts64(sb + AL + so[q], l);
        }
        #pragma unroll
        for (int q = 0; q < 4; q++) {
            sx[q] += xr[q].x + xr[q].y + xr[q].z + xr[q].w;
            uint2 h, l;
            split4(xr[q], h, l);
            sts64(sb + BH + so[q], h);
            sts64(sb + BL + so[q], l);
        }
        __syncthreads();

        // prefetch next chunk (lands during this chunk's MMA drain)
        if (ch < 15) {
            const int kc = (ch + 1) * 16;
            #pragma unroll
            for (int q = 0; q < 4; q++) {
                wr[q] = wg[(m0 + rw[q]) * 256 + kc + cw[q]];
                xr[q] = xg[rw[q] * 256 + kc + cw[q]];
            }
        }

        // 4 k16 steps: 24 LDSM + 48 HMMA per warp per chunk
        #pragma unroll
        for (int kk = 0; kk < 4; kk++) {
            const uint32_t kb = kk * 32;
            const uint32_t arow = (uint32_t)(wm * 32 + (lane & 15));
            const uint32_t akb  = kb + ((lane >> 4) << 4);
            uint32_t ah0[4], ah1[4], al0[4], al1[4], bh[4], bl[4];
            ldsm4(ah0, sb + AH + swz(arow * 128 + akb));
            ldsm4(ah1, sb + AH + swz((arow + 16) * 128 + akb));
            ldsm4(al0, sb + AL + swz(arow * 128 + akb));
            ldsm4(al1, sb + AL + swz((arow + 16) * 128 + akb));
            const uint32_t brow = (uint32_t)(wn * 16 + ((lane >> 4) << 3) + (lane & 7));
            const uint32_t bkb  = kb + (((lane >> 3) & 1) << 4);
            ldsm4(bh, sb + BH + swz(brow * 128 + bkb));
            ldsm4(bl, sb + BL + swz(brow * 128 + bkb));

            #pragma unroll
            for (int ni = 0; ni < 2; ni++) {
                mma16816(acc[0][ni], ah0, bh[2 * ni], bh[2 * ni + 1]);
                mma16816(acc[0][ni], ah0, bl[2 * ni], bl[2 * ni + 1]);
                mma16816(acc[0][ni], al0, bh[2 * ni], bh[2 * ni + 1]);
                mma16816(acc[1][ni], ah1, bh[2 * ni], bh[2 * ni + 1]);
                mma16816(acc[1][ni], ah1, bl[2 * ni], bl[2 * ni + 1]);
                mma16816(acc[1][ni], al1, bh[2 * ni], bh[2 * ni + 1]);
            }
        }
    }
    __syncthreads();   // LDSM of last chunk done in-warp; barrier frees smem

    // ---------------- fused prep: c[b, e] for this CTA's expert ----------------
    float* sums = reinterpret_cast<float*>(smem);              // [64][16]
    #pragma unroll
    for (int q = 0; q < 4; q++) sums[rw[q] * 16 + (tid & 15)] = sx[q];
    __syncthreads();

    float* cs = reinterpret_cast<float*>(smem + CS_OFF);       // [64]
    if (tid < 64) {
        float s = 0.f;
        #pragma unroll
        for (int i = 0; i < 16; i++) s += sums[tid * 16 + i];
        const float pm = s * (1.f / (float)kIn);
        float r[kH];
        #pragma unroll
        for (int j = 0; j < kH; j++)
            r[j] = fmaxf(tanhf(fmaf(pm, W_ih[j], b_ih[j] + b_hh[j])), 0.f);
        float logits[kE], mx = -1e30f;
        #pragma unroll
        for (int f = 0; f < kE; f++) {
            float l = b_att[f];
            #pragma unroll
            for (int j = 0; j < kH; j++) l = fmaf(r[j], W_att[f * kH + j], l);
            logits[f] = l;
            mx = fmaxf(mx, l);
        }
        float se = 0.f, att[kE];
        #pragma unroll
        for (int f = 0; f < kE; f++) { att[f] = expf(logits[f] - mx); se += att[f]; }
        const float inv = 1.f / se;
        float c = 0.f;
        #pragma unroll
        for (int f = 0; f < kE; f++) c = fmaf(att[f] * inv, align_conv[f * kE + e], c);
        cs[tid] = c;
    }
    __syncthreads();

    // ---------------- transpose accumulators to [b][o] via smem ----------------
    float* tr = reinterpret_cast<float*>(smem);                // [64 b][68 pad]
    #pragma unroll
    for (int mi = 0; mi < 2; mi++)
        #pragma unroll
        for (int ni = 0; ni < 2; ni++) {
            const int r0 = wm * 32 + mi * 16 + (lane >> 2);
            const int c0 = wn * 16 + ni * 8 + (lane & 3) * 2;
            tr[c0 * 68 + r0]            = acc[mi][ni][0];
            tr[(c0 + 1) * 68 + r0]      = acc[mi][ni][1];
            tr[c0 * 68 + r0 + 8]        = acc[mi][ni][2];
            tr[(c0 + 1) * 68 + r0 + 8]  = acc[mi][ni][3];
        }
    __syncthreads();

    const int b = tid >> 2;          // 4 threads per sample
    const float s = cs[b];

    if (e < 7) {
        // producer: store scaled partial, then release-signal the o-tile flag
        #pragma unroll
        for (int it = 0; it < 4; it++) {
            const int o4 = (tid & 3) + it * 4;
            float4 v = *reinterpret_cast<const float4*>(&tr[b * 68 + o4 * 4]);
            v.x *= s; v.y *= s; v.z *= s; v.w *= s;
            *reinterpret_cast<float4*>(
                &g_part[e * (kB * kOut) + b * kOut + ob + o4 * 4]) = v;
        }
        __threadfence();
        __syncthreads();
        if (tid == 0)
            asm volatile("red.release.gpu.global.add.s32 [%0], 1;"
                         :: "l"(&g_flag[t]) : "memory");
    } else {
        // reducer: wait for 7 producers of this o-tile, combine, write d_out
        if (tid == 0) {
            int v;
            do {
                asm volatile("ld.acquire.gpu.global.b32 %0, [%1];"
                             : "=r"(v) : "l"(&g_flag[t]) : "memory");
                if (v != 7) __nanosleep(64);
            } while (v != 7);
            g_flag[t] = 0;   // reset for next graph replay
        }
        __syncthreads();
        __threadfence();

        const float4* gp4 = reinterpret_cast<const float4*>(g_part);
        #pragma unroll
        for (int it = 0; it < 4; it++) {
            const int o4 = (tid & 3) + it * 4;
            float4 v = *reinterpret_cast<const float4*>(&tr[b * 68 + o4 * 4]);
            v.x *= s; v.y *= s; v.z *= s; v.w *= s;
            const int base = (b * kOut + ob) >> 2;
            #pragma unroll
            for (int e2 = 0; e2 < 7; e2++) {
                float4 p = __ldcg(&gp4[e2 * (kB * kOut / 4) + base + o4]);
                v.x += p.x; v.y += p.y; v.z += p.z; v.w += p.w;
            }
            *reinterpret_cast<float4*>(&out[b * kOut + ob + o4 * 4]) = v;
        }
    }
}

// ---------------------------------------------------------------------------
extern "C" void kernel_launch(void* const* d_in, const int* in_sizes, int n_in,
                              void* d_out, int out_size) {
    const float* x          = (const float*)d_in[0];
    const float* weight     = (const float*)d_in[1];
    const float* align_conv = (const float*)d_in[2];
    const float* W_ih       = (const float*)d_in[3];
    // d_in[4] = W_hh — unused (h0 = 0)
    const float* b_ih       = (const float*)d_in[5];
    const float* b_hh       = (const float*)d_in[6];
    const float* W_att      = (const float*)d_in[7];
    const float* b_att      = (const float*)d_in[8];
    float* out = (float*)d_out;

    cudaFuncSetAttribute(gemm_kernel, cudaFuncAttributeMaxDynamicSharedMemorySize,
                         SMEM_TOTAL);

    gemm_kernel<<<128, 256, SMEM_TOTAL>>>(x, weight, align_conv,
                                          W_ih, b_ih, b_hh, W_att, b_att, out);
}

// round 12
// speedup vs baseline: 1.0784x; 1.0784x over previous
#include <cuda_runtime.h>
#include <cuda_bf16.h>
#include <math.h>
#include <stdint.h>

constexpr int kB   = 64;
constexpr int kIn  = 1024;
constexpr int kOut = 1024;
constexpr int kE   = 8;
constexpr int kH   = 8;

// 16 slots = 8 experts x 2 k-halves, raw (unscaled) partials
__device__ float g_part[16 * kB * kOut];   // 4 MB

// ---------------------------------------------------------------------------
// helpers
// ---------------------------------------------------------------------------
__device__ __forceinline__ uint32_t smem_u32(const void* p) {
    uint32_t a;
    asm("{ .reg .u64 t; cvta.to.shared.u64 t, %1; cvt.u32.u64 %0, t; }"
        : "=r"(a) : "l"(p));
    return a;
}
__device__ __forceinline__ uint32_t swz(uint32_t off) {   // SW128 (Swizzle<3,4,3>)
    return off ^ ((off >> 3) & 0x70);
}
__device__ __forceinline__ void sts64(uint32_t addr, uint2 v) {
    asm volatile("st.shared.v2.u32 [%0], {%1,%2};" :: "r"(addr), "r"(v.x), "r"(v.y));
}
__device__ __forceinline__ void ldsm4(uint32_t* r, uint32_t addr) {
    asm volatile("ldmatrix.sync.aligned.m8n8.x4.shared.b16 {%0,%1,%2,%3}, [%4];"
                 : "=r"(r[0]), "=r"(r[1]), "=r"(r[2]), "=r"(r[3]) : "r"(addr));
}
__device__ __forceinline__ void mma16816(float* d, const uint32_t* a,
                                         uint32_t b0, uint32_t b1) {
    asm volatile(
        "mma.sync.aligned.m16n8k16.row.col.f32.bf16.bf16.f32 "
        "{%0,%1,%2,%3}, {%4,%5,%6,%7}, {%8,%9}, {%0,%1,%2,%3};"
        : "+f"(d[0]), "+f"(d[1]), "+f"(d[2]), "+f"(d[3])
        : "r"(a[0]), "r"(a[1]), "r"(a[2]), "r"(a[3]), "r"(b0), "r"(b1));
}
__device__ __forceinline__ void split4(float4 f, uint2& h, uint2& l) {
    __nv_bfloat162 h01 = __floats2bfloat162_rn(f.x, f.y);
    __nv_bfloat162 h23 = __floats2bfloat162_rn(f.z, f.w);
    float a0 = __bfloat162float(h01.x), a1 = __bfloat162float(h01.y);
    float a2 = __bfloat162float(h23.x), a3 = __bfloat162float(h23.y);
    __nv_bfloat162 l01 = __floats2bfloat162_rn(f.x - a0, f.y - a1);
    __nv_bfloat162 l23 = __floats2bfloat162_rn(f.z - a2, f.w - a3);
    h = make_uint2(*reinterpret_cast<uint32_t*>(&h01), *reinterpret_cast<uint32_t*>(&h23));
    l = make_uint2(*reinterpret_cast<uint32_t*>(&l01), *reinterpret_cast<uint32_t*>(&l23));
}

// ---------------------------------------------------------------------------
// Split-K GEMM. 256 CTAs x 256 thr, 2 CTAs/SM (decoupled barriers -> the two
// resident CTAs overlap convert/STS phases with MMA phases). Each CTA:
// m64(eo) x n64(b) x K512 (k-half), KC=64, 8 chunks, R4 loop structure.
// ---------------------------------------------------------------------------
constexpr int STAGE = 32768;
constexpr int AH = 0, AL = 8192, BH = 16384, BL = 24576;
constexpr int SMEM_TOTAL = 2 * STAGE;      // 65536

__global__ __launch_bounds__(256, 2)
void gemm_kernel(const float* __restrict__ x, const float* __restrict__ w) {
    extern __shared__ char smem[];
    const uint32_t sbase = smem_u32(smem);
    const int tid  = threadIdx.x;
    const int lane = tid & 31;
    const int wid  = tid >> 5;
    const int wm   = wid & 1;        // m half (32 rows)
    const int wn   = wid >> 1;       // n quarter (16 cols)

    const int e    = blockIdx.x >> 5;          // expert
    const int t    = (blockIdx.x >> 1) & 15;   // o-tile
    const int kh   = blockIdx.x & 1;           // k-half
    const int ob   = t * 64;
    const int m0   = e * kOut + ob;            // global w row base
    const int kb0  = kh * 128;                 // float4 col base of this k-half

    float acc[2][2][4];
    #pragma unroll
    for (int i = 0; i < 2; i++)
        #pragma unroll
        for (int j = 0; j < 2; j++)
            #pragma unroll
            for (int c = 0; c < 4; c++) acc[i][j][c] = 0.f;

    const float4* wg = reinterpret_cast<const float4*>(w);
    const float4* xg = reinterpret_cast<const float4*>(x);
    int rw[4], cw[4];
    #pragma unroll
    for (int q = 0; q < 4; q++) { int j = tid + q * 256; rw[q] = j >> 4; cw[q] = j & 15; }
    uint32_t so[4];
    #pragma unroll
    for (int q = 0; q < 4; q++) so[q] = swz((uint32_t)(rw[q] * 128 + cw[q] * 8));

    float4 wr[4], xr[4];
    #pragma unroll
    for (int q = 0; q < 4; q++) {
        wr[q] = wg[(m0 + rw[q]) * 256 + kb0 + cw[q]];
        xr[q] = xg[rw[q] * 256 + kb0 + cw[q]];
    }

    for (int ch = 0; ch < 8; ch++) {
        const uint32_t sb = sbase + (uint32_t)((ch & 1) * STAGE);

        // convert + swizzled STS
        #pragma unroll
        for (int q = 0; q < 4; q++) {
            uint2 h, l;
            split4(wr[q], h, l);
            sts64(sb + AH + so[q], h);
            sts64(sb + AL + so[q], l);
        }
        #pragma unroll
        for (int q = 0; q < 4; q++) {
            uint2 h, l;
            split4(xr[q], h, l);
            sts64(sb + BH + so[q], h);
            sts64(sb + BL + so[q], l);
        }
        __syncthreads();

        // prefetch next chunk (lands during this chunk's MMA drain)
        if (ch < 7) {
            const int kc = kb0 + (ch + 1) * 16;
            #pragma unroll
            for (int q = 0; q < 4; q++) {
                wr[q] = wg[(m0 + rw[q]) * 256 + kc + cw[q]];
                xr[q] = xg[rw[q] * 256 + kc + cw[q]];
            }
        }

        // 4 k16 steps: 24 LDSM + 48 HMMA per warp per chunk
        #pragma unroll
        for (int kk = 0; kk < 4; kk++) {
            const uint32_t kb = kk * 32;
            const uint32_t arow = (uint32_t)(wm * 32 + (lane & 15));
            const uint32_t akb  = kb + ((lane >> 4) << 4);
            uint32_t ah0[4], ah1[4], al0[4], al1[4], bh[4], bl[4];
            ldsm4(ah0, sb + AH + swz(arow * 128 + akb));
            ldsm4(ah1, sb + AH + swz((arow + 16) * 128 + akb));
            ldsm4(al0, sb + AL + swz(arow * 128 + akb));
            ldsm4(al1, sb + AL + swz((arow + 16) * 128 + akb));
            const uint32_t brow = (uint32_t)(wn * 16 + ((lane >> 4) << 3) + (lane & 7));
            const uint32_t bkb  = kb + (((lane >> 3) & 1) << 4);
            ldsm4(bh, sb + BH + swz(brow * 128 + bkb));
            ldsm4(bl, sb + BL + swz(brow * 128 + bkb));

            #pragma unroll
            for (int ni = 0; ni < 2; ni++) {
                mma16816(acc[0][ni], ah0, bh[2 * ni], bh[2 * ni + 1]);
                mma16816(acc[0][ni], ah0, bl[2 * ni], bl[2 * ni + 1]);
                mma16816(acc[0][ni], al0, bh[2 * ni], bh[2 * ni + 1]);
                mma16816(acc[1][ni], ah1, bh[2 * ni], bh[2 * ni + 1]);
                mma16816(acc[1][ni], ah1, bl[2 * ni], bl[2 * ni + 1]);
                mma16816(acc[1][ni], al1, bh[2 * ni], bh[2 * ni + 1]);
            }
        }
        __syncthreads();   // reads of buf ch&1 done before rewrite next iter
    }

    // ---------------- transpose accumulators to [b][o] via smem, raw STG ------
    float* tr = reinterpret_cast<float*>(smem);                // [64 b][68 pad]
    #pragma unroll
    for (int mi = 0; mi < 2; mi++)
        #pragma unroll
        for (int ni = 0; ni < 2; ni++) {
            const int r0 = wm * 32 + mi * 16 + (lane >> 2);
            const int c0 = wn * 16 + ni * 8 + (lane & 3) * 2;
            tr[c0 * 68 + r0]            = acc[mi][ni][0];
            tr[(c0 + 1) * 68 + r0]      = acc[mi][ni][1];
            tr[c0 * 68 + r0 + 8]        = acc[mi][ni][2];
            tr[(c0 + 1) * 68 + r0 + 8]  = acc[mi][ni][3];
        }
    __syncthreads();

    const int b    = tid >> 2;       // 4 threads per sample
    const int slot = e * 2 + kh;
    #pragma unroll
    for (int it = 0; it < 4; it++) {
        const int o4 = (tid & 3) + it * 4;
        float4 v = *reinterpret_cast<const float4*>(&tr[b * 68 + o4 * 4]);
        *reinterpret_cast<float4*>(
            &g_part[slot * (kB * kOut) + b * kOut + ob + o4 * 4]) = v;
    }
}

// ---------------------------------------------------------------------------
// Reduce kernel: one block per sample b. Computes the attention coefficients
// c[b, e] (mean -> tanh RNN -> relu -> softmax -> align) and combines the 16
// raw partial slots into d_out.
// ---------------------------------------------------------------------------
__global__ __launch_bounds__(256)
void reduce_kernel(const float* __restrict__ x,
                   const float* __restrict__ align_conv,
                   const float* __restrict__ W_ih, const float* __restrict__ b_ih,
                   const float* __restrict__ b_hh, const float* __restrict__ W_att,
                   const float* __restrict__ b_att, float* __restrict__ out) {
    __shared__ float red[8];
    __shared__ float cs[kE];
    const int b   = blockIdx.x;
    const int tid = threadIdx.x;

    // mean over x[b, :]
    const float4* xg = reinterpret_cast<const float4*>(x + b * kIn);
    float4 xv = xg[tid];
    float s = xv.x + xv.y + xv.z + xv.w;
    #pragma unroll
    for (int off = 16; off; off >>= 1) s += __shfl_xor_sync(0xffffffffu, s, off);
    if ((tid & 31) == 0) red[tid >> 5] = s;
    __syncthreads();

    if (tid == 0) {
        float tot = 0.f;
        #pragma unroll
        for (int i = 0; i < 8; i++) tot += red[i];
        const float pm = tot * (1.f / (float)kIn);
        float r[kH];
        #pragma unroll
        for (int j = 0; j < kH; j++)
            r[j] = fmaxf(tanhf(fmaf(pm, W_ih[j], b_ih[j] + b_hh[j])), 0.f);
        float logits[kE], mx = -1e30f;
        #pragma unroll
        for (int f = 0; f < kE; f++) {
            float l = b_att[f];
            #pragma unroll
            for (int j = 0; j < kH; j++) l = fmaf(r[j], W_att[f * kH + j], l);
            logits[f] = l;
            mx = fmaxf(mx, l);
        }
        float se = 0.f, att[kE];
        #pragma unroll
        for (int f = 0; f < kE; f++) { att[f] = expf(logits[f] - mx); se += att[f]; }
        const float inv = 1.f / se;
        #pragma unroll
        for (int e = 0; e < kE; e++) {
            float c = 0.f;
            #pragma unroll
            for (int f = 0; f < kE; f++)
                c = fmaf(att[f] * inv, align_conv[f * kE + e], c);
            cs[e] = c;
        }
    }
    __syncthreads();

    // combine 16 slots: y[b, o] = sum_e c[b,e] * (part[e,k0] + part[e,k1])
    const float4* p4 = reinterpret_cast<const float4*>(g_part);
    float4 acc = make_float4(0.f, 0.f, 0.f, 0.f);
    const int base = b * (kOut / 4) + tid;
    #pragma unroll
    for (int slot = 0; slot < 16; slot++) {
        const float c = cs[slot >> 1];
        float4 v = __ldcg(&p4[slot * (kB * kOut / 4) + base]);
        acc.x = fmaf(c, v.x, acc.x);
        acc.y = fmaf(c, v.y, acc.y);
        acc.z = fmaf(c, v.z, acc.z);
        acc.w = fmaf(c, v.w, acc.w);
    }
    reinterpret_cast<float4*>(out)[base] = acc;
}

// ---------------------------------------------------------------------------
extern "C" void kernel_launch(void* const* d_in, const int* in_sizes, int n_in,
                              void* d_out, int out_size) {
    const float* x          = (const float*)d_in[0];
    const float* weight     = (const float*)d_in[1];
    const float* align_conv = (const float*)d_in[2];
    const float* W_ih       = (const float*)d_in[3];
    // d_in[4] = W_hh — unused (h0 = 0)
    const float* b_ih       = (const float*)d_in[5];
    const float* b_hh       = (const float*)d_in[6];
    const float* W_att      = (const float*)d_in[7];
    const float* b_att      = (const float*)d_in[8];
    float* out = (float*)d_out;

    cudaFuncSetAttribute(gemm_kernel, cudaFuncAttributeMaxDynamicSharedMemorySize,
                         SMEM_TOTAL);

    gemm_kernel<<<256, 256, SMEM_TOTAL>>>(x, weight);
    reduce_kernel<<<kB, 256>>>(x, align_conv, W_ih, b_ih, b_hh, W_att, b_att, out);
}

// round 15
// speedup vs baseline: 1.1969x; 1.1099x over previous
#include <cuda_runtime.h>
#include <cuda_fp16.h>
#include <math.h>
#include <stdint.h>

constexpr int kB   = 64;
constexpr int kIn  = 1024;
constexpr int kOut = 1024;
constexpr int kE   = 8;
constexpr int kH   = 8;

// 16 slots = 8 experts x 2 k-halves, raw (unscaled) partials
__device__ float g_part[16 * kB * kOut];   // 4 MB

// ---------------------------------------------------------------------------
// helpers
// ---------------------------------------------------------------------------
__device__ __forceinline__ uint32_t smem_u32(const void* p) {
    uint32_t a;
    asm("{ .reg .u64 t; cvta.to.shared.u64 t, %1; cvt.u32.u64 %0, t; }"
        : "=r"(a) : "l"(p));
    return a;
}
__device__ __forceinline__ uint32_t swz(uint32_t off) {   // SW128 (Swizzle<3,4,3>)
    return off ^ ((off >> 3) & 0x70);
}
__device__ __forceinline__ void sts64(uint32_t addr, uint2 v) {
    asm volatile("st.shared.v2.u32 [%0], {%1,%2};" :: "r"(addr), "r"(v.x), "r"(v.y));
}
__device__ __forceinline__ void ldsm4(uint32_t* r, uint32_t addr) {
    asm volatile("ldmatrix.sync.aligned.m8n8.x4.shared.b16 {%0,%1,%2,%3}, [%4];"
                 : "=r"(r[0]), "=r"(r[1]), "=r"(r[2]), "=r"(r[3]) : "r"(addr));
}
__device__ __forceinline__ void mma16816(float* d, const uint32_t* a,
                                         uint32_t b0, uint32_t b1) {
    asm volatile(
        "mma.sync.aligned.m16n8k16.row.col.f32.f16.f16.f32 "
        "{%0,%1,%2,%3}, {%4,%5,%6,%7}, {%8,%9}, {%0,%1,%2,%3};"
        : "+f"(d[0]), "+f"(d[1]), "+f"(d[2]), "+f"(d[3])
        : "r"(a[0]), "r"(a[1]), "r"(a[2]), "r"(a[3]), "r"(b0), "r"(b1));
}
// w: exact 2-term fp16 split (hi + residual)
__device__ __forceinline__ void split4h(float4 f, uint2& h, uint2& l) {
    __half2 h01 = __floats2half2_rn(f.x, f.y);
    __half2 h23 = __floats2half2_rn(f.z, f.w);
    float2 a = __half22float2(h01);
    float2 b = __half22float2(h23);
    __half2 l01 = __floats2half2_rn(f.x - a.x, f.y - a.y);
    __half2 l23 = __floats2half2_rn(f.z - b.x, f.w - b.y);
    h = make_uint2(*reinterpret_cast<uint32_t*>(&h01), *reinterpret_cast<uint32_t*>(&h23));
    l = make_uint2(*reinterpret_cast<uint32_t*>(&l01), *reinterpret_cast<uint32_t*>(&l23));
}
// x: single fp16 rounding
__device__ __forceinline__ uint2 cvt4h(float4 f) {
    __half2 h01 = __floats2half2_rn(f.x, f.y);
    __half2 h23 = __floats2half2_rn(f.z, f.w);
    return make_uint2(*reinterpret_cast<uint32_t*>(&h01),
                      *reinterpret_cast<uint32_t*>(&h23));
}

// ---------------------------------------------------------------------------
// Split-K GEMM, fp16 2-term. 256 CTAs x 256 thr, 2 CTAs/SM.
// CTA tile m64(eo) x n64(b) x K512 (k-half), KC=64, 8 chunks.
// smem/stage: A_hi 8K | A_lo 8K | B_hi 8K = 24 KB; 2 stages = 48 KB.
// ---------------------------------------------------------------------------
constexpr int STAGE = 24576;
constexpr int AH = 0, AL = 8192, BH = 16384;
constexpr int SMEM_TOTAL = 2 * STAGE;      // 49152

__global__ __launch_bounds__(256, 2)
void gemm_kernel(const float* __restrict__ x, const float* __restrict__ w) {
    extern __shared__ char smem[];
    const uint32_t sbase = smem_u32(smem);
    const int tid  = threadIdx.x;
    const int lane = tid & 31;
    const int wid  = tid >> 5;
    const int wm   = wid & 1;        // m half (32 rows)
    const int wn   = wid >> 1;       // n quarter (16 cols)

    const int e    = blockIdx.x >> 5;          // expert
    const int t    = (blockIdx.x >> 1) & 15;   // o-tile
    const int kh   = blockIdx.x & 1;           // k-half
    const int ob   = t * 64;
    const int m0   = e * kOut + ob;            // global w row base
    const int kb0  = kh * 128;                 // float4 col base of this k-half

    float acc[2][2][4];
    #pragma unroll
    for (int i = 0; i < 2; i++)
        #pragma unroll
        for (int j = 0; j < 2; j++)
            #pragma unroll
            for (int c = 0; c < 4; c++) acc[i][j][c] = 0.f;

    const float4* wg = reinterpret_cast<const float4*>(w);
    const float4* xg = reinterpret_cast<const float4*>(x);
    int rw[4], cw[4];
    #pragma unroll
    for (int q = 0; q < 4; q++) { int j = tid + q * 256; rw[q] = j >> 4; cw[q] = j & 15; }
    uint32_t so[4];
    #pragma unroll
    for (int q = 0; q < 4; q++) so[q] = swz((uint32_t)(rw[q] * 128 + cw[q] * 8));

    float4 wr[4], xr[4];
    #pragma unroll
    for (int q = 0; q < 4; q++) {
        wr[q] = wg[(m0 + rw[q]) * 256 + kb0 + cw[q]];
        xr[q] = xg[rw[q] * 256 + kb0 + cw[q]];
    }

    for (int ch = 0; ch < 8; ch++) {
        const uint32_t sb = sbase + (uint32_t)((ch & 1) * STAGE);

        // convert + swizzled STS
        #pragma unroll
        for (int q = 0; q < 4; q++) {
            uint2 h, l;
            split4h(wr[q], h, l);
            sts64(sb + AH + so[q], h);
            sts64(sb + AL + so[q], l);
        }
        #pragma unroll
        for (int q = 0; q < 4; q++)
            sts64(sb + BH + so[q], cvt4h(xr[q]));
        __syncthreads();

        // prefetch next chunk (lands during this chunk's MMA drain)
        if (ch < 7) {
            const int kc = kb0 + (ch + 1) * 16;
            #pragma unroll
            for (int q = 0; q < 4; q++) {
                wr[q] = wg[(m0 + rw[q]) * 256 + kc + cw[q]];
                xr[q] = xg[rw[q] * 256 + kc + cw[q]];
            }
        }

        // 4 k16 steps: 20 LDSM + 32 HMMA per warp per chunk
        #pragma unroll
        for (int kk = 0; kk < 4; kk++) {
            const uint32_t kb = kk * 32;
            const uint32_t arow = (uint32_t)(wm * 32 + (lane & 15));
            const uint32_t akb  = kb + ((lane >> 4) << 4);
            uint32_t ah0[4], ah1[4], al0[4], al1[4], bh[4];
            ldsm4(ah0, sb + AH + swz(arow * 128 + akb));
            ldsm4(ah1, sb + AH + swz((arow + 16) * 128 + akb));
            ldsm4(al0, sb + AL + swz(arow * 128 + akb));
            ldsm4(al1, sb + AL + swz((arow + 16) * 128 + akb));
            const uint32_t brow = (uint32_t)(wn * 16 + ((lane >> 4) << 3) + (lane & 7));
            const uint32_t bkb  = kb + (((lane >> 3) & 1) << 4);
            ldsm4(bh, sb + BH + swz(brow * 128 + bkb));

            #pragma unroll
            for (int ni = 0; ni < 2; ni++) {
                mma16816(acc[0][ni], ah0, bh[2 * ni], bh[2 * ni + 1]);
                mma16816(acc[0][ni], al0, bh[2 * ni], bh[2 * ni + 1]);
                mma16816(acc[1][ni], ah1, bh[2 * ni], bh[2 * ni + 1]);
                mma16816(acc[1][ni], al1, bh[2 * ni], bh[2 * ni + 1]);
            }
        }
        __syncthreads();   // reads of buf ch&1 done before rewrite next iter
    }

    // ---------------- transpose accumulators to [b][o] via smem, raw STG ------
    float* tr = reinterpret_cast<float*>(smem);                // [64 b][68 pad]
    #pragma unroll
    for (int mi = 0; mi < 2; mi++)
        #pragma unroll
        for (int ni = 0; ni < 2; ni++) {
            const int r0 = wm * 32 + mi * 16 + (lane >> 2);
            const int c0 = wn * 16 + ni * 8 + (lane & 3) * 2;
            tr[c0 * 68 + r0]            = acc[mi][ni][0];
            tr[(c0 + 1) * 68 + r0]      = acc[mi][ni][1];
            tr[c0 * 68 + r0 + 8]        = acc[mi][ni][2];
            tr[(c0 + 1) * 68 + r0 + 8]  = acc[mi][ni][3];
        }
    __syncthreads();

    const int b    = tid >> 2;       // 4 threads per sample
    const int slot = e * 2 + kh;
    #pragma unroll
    for (int it = 0; it < 4; it++) {
        const int o4 = (tid & 3) + it * 4;
        float4 v = *reinterpret_cast<const float4*>(&tr[b * 68 + o4 * 4]);
        *reinterpret_cast<float4*>(
            &g_part[slot * (kB * kOut) + b * kOut + ob + o4 * 4]) = v;
    }
}

// ---------------------------------------------------------------------------
// Reduce: 256 blocks (4 per sample) x 128 thr. Each block redundantly computes
// c[b, :] (cheap scalar chain) then combines the 16 raw slots for its o-quarter.
// ---------------------------------------------------------------------------
__global__ __launch_bounds__(128)
void reduce_kernel(const float* __restrict__ x,
                   const float* __restrict__ align_conv,
                   const float* __restrict__ W_ih, const float* __restrict__ b_ih,
                   const float* __restrict__ b_hh, const float* __restrict__ W_att,
                   const float* __restrict__ b_att, float* __restrict__ out) {
    __shared__ float red[4];
    __shared__ float cs[kE];
    const int b   = blockIdx.x >> 2;
    const int oq  = blockIdx.x & 3;
    const int tid = threadIdx.x;

    // mean over x[b, :] — 256 float4 read by 128 threads
    const float4* xg = reinterpret_cast<const float4*>(x + b * kIn);
    float4 v1 = xg[tid];
    float4 v2 = xg[tid + 128];
    float s = v1.x + v1.y + v1.z + v1.w + v2.x + v2.y + v2.z + v2.w;
    #pragma unroll
    for (int off = 16; off; off >>= 1) s += __shfl_xor_sync(0xffffffffu, s, off);
    if ((tid & 31) == 0) red[tid >> 5] = s;
    __syncthreads();

    if (tid == 0) {
        const float pm = (red[0] + red[1] + red[2] + red[3]) * (1.f / (float)kIn);
        float r[kH];
        #pragma unroll
        for (int j = 0; j < kH; j++)
            r[j] = fmaxf(tanhf(fmaf(pm, W_ih[j], b_ih[j] + b_hh[j])), 0.f);
        float logits[kE], mx = -1e30f;
        #pragma unroll
        for (int f = 0; f < kE; f++) {
            float l = b_att[f];
            #pragma unroll
            for (int j = 0; j < kH; j++) l = fmaf(r[j], W_att[f * kH + j], l);
            logits[f] = l;
            mx = fmaxf(mx, l);
        }
        float se = 0.f, att[kE];
        #pragma unroll
        for (int f = 0; f < kE; f++) { att[f] = expf(logits[f] - mx); se += att[f]; }
        const float inv = 1.f / se;
        #pragma unroll
        for (int e = 0; e < kE; e++) {
            float c = 0.f;
            #pragma unroll
            for (int f = 0; f < kE; f++)
                c = fmaf(att[f] * inv, align_conv[f * kE + e], c);
            cs[e] = c;
        }
    }
    __syncthreads();

    // combine 16 slots for this block's o-quarter (64 float4)
    if (tid < 64) {
        const float4* p4 = reinterpret_cast<const float4*>(g_part);
        const int base = b * (kOut / 4) + oq * 64 + tid;
        float4 acc = make_float4(0.f, 0.f, 0.f, 0.f);
        #pragma unroll
        for (int slot = 0; slot < 16; slot++) {
            const float c = cs[slot >> 1];
            float4 v = __ldcg(&p4[slot * (kB * kOut / 4) + base]);
            acc.x = fmaf(c, v.x, acc.x);
            acc.y = fmaf(c, v.y, acc.y);
            acc.z = fmaf(c, v.z, acc.z);
            acc.w = fmaf(c, v.w, acc.w);
        }
        reinterpret_cast<float4*>(out)[base] = acc;
    }
}

// ---------------------------------------------------------------------------
extern "C" void kernel_launch(void* const* d_in, const int* in_sizes, int n_in,
                              void* d_out, int out_size) {
    const float* x          = (const float*)d_in[0];
    const float* weight     = (const float*)d_in[1];
    const float* align_conv = (const float*)d_in[2];
    const float* W_ih       = (const float*)d_in[3];
    // d_in[4] = W_hh — unused (h0 = 0)
    const float* b_ih       = (const float*)d_in[5];
    const float* b_hh       = (const float*)d_in[6];
    const float* W_att      = (const float*)d_in[7];
    const float* b_att      = (const float*)d_in[8];
    float* out = (float*)d_out;

    cudaFuncSetAttribute(gemm_kernel, cudaFuncAttributeMaxDynamicSharedMemorySize,
                         SMEM_TOTAL);

    gemm_kernel<<<256, 256, SMEM_TOTAL>>>(x, weight);
    reduce_kernel<<<256, 128>>>(x, align_conv, W_ih, b_ih, b_hh, W_att, b_att, out);
}